// round 14
// baseline (speedup 1.0000x reference)
#include <cuda_runtime.h>

// Problem constants
#define W_DIM 512
#define H_DIM 512
#define B_DIM 8
#define C_DIM 32
#define NBLK  128           // scan blocks: 8 batches * 16 row-tiles
#define NHELP 20            // helper (transpose) blocks on otherwise-idle SMs
#define NTHR  256
#define NCHK  4             // w-chunks of 128 columns
#define CHKW  128
#define TILES_PER_CHUNK (H_DIM * B_DIM)   // 4096 (one 128w x 32c tile per (h,b))

// Scratch: transposed input/output in (W, B, H, C) layout, C contiguous.
__device__ float    g_Xt[W_DIM * B_DIM * H_DIM * C_DIM];   // 256 MB
__device__ float    g_Yt[W_DIM * B_DIM * H_DIM * C_DIM];   // 256 MB
__device__ unsigned g_progress[NBLK];    // monotonic, +512/run (proven)
__device__ unsigned g_xt_ready[NCHK];    // monotonic, +NHELP/run
__device__ unsigned g_out_ready[NCHK];   // monotonic, +NBLK/run

// ---- fast math -------------------------------------------------------------
__device__ __forceinline__ float tanh_fast(float x) {
    float y; asm("tanh.approx.f32 %0, %1;" : "=f"(y) : "f"(x)); return y;
}
__device__ __forceinline__ float sigmoid_fast(float x) {
    return fmaf(0.5f, tanh_fast(0.5f * x), 0.5f);
}

// Release-ordered atomics at GPU scope (proven R10/R12 protocol): issued by
// the leader AFTER __syncthreads, the cumulative release covers all of the
// block's prior global stores.
__device__ __forceinline__ void atom_rel_exch(unsigned* p, unsigned v) {
    unsigned old;
    asm volatile("atom.release.gpu.global.exch.b32 %0, [%1], %2;"
                 : "=r"(old) : "l"(p), "r"(v) : "memory");
}
__device__ __forceinline__ void atom_rel_add(unsigned* p, unsigned v) {
    unsigned old;
    asm volatile("atom.release.gpu.global.add.u32 %0, [%1], %2;"
                 : "=r"(old) : "l"(p), "r"(v) : "memory");
}

// ---------------------------------------------------------------------------
// smem layout (floats) — scan blocks. Helper blocks reuse the same dynamic
// allocation as a 32 x 132 transpose tile (4224 floats <= SM_FLOATS).
// ---------------------------------------------------------------------------
#define SM_WIH  0
#define SM_WHH  (SM_WIH + 96 * 100)
#define SM_BUFA (SM_WHH + 96 * 36)
#define SM_BUFB (SM_BUFA + 34 * 32)
#define SM_CUR  (SM_BUFB + 34 * 32)
#define SM_FLOATS (SM_CUR + 32 * 32)

// ===========================================================================
// HELPER BLOCKS — transposes on the 20 idle SMs (R12-proven tile phases,
// software-pipelined global preload so throughput-, not latency-bound).
// ===========================================================================
__device__ __forceinline__ void tin_preload(
    const float* __restrict__ states, int w0, int idx, int t, float4 v[4])
{
    const int h = idx & 511, b = idx >> 9;
    const int c = t >> 3, w8 = t & 7;
    const size_t base = ((size_t)(b * 32 + c) * 512 + h) * 512 + w0;
#pragma unroll
    for (int k = 0; k < 4; ++k)
        v[k] = *(const float4*)&states[base + w8 * 4 + k * 32];
}

__device__ __forceinline__ void tout_preload(int w0, int idx, int t, float4 v[4])
{
    const int h = idx & 511, b = idx >> 9;
    const int wl = t >> 1, chalf = t & 1;
    const size_t base = ((size_t)((w0 + wl) * 8 + b) * 512 + h) * 32 + chalf * 16;
#pragma unroll
    for (int k = 0; k < 4; ++k)
        v[k] = *(const float4*)&g_Yt[base + k * 4];
}

__device__ void helper_body(const float* __restrict__ states,
                            float* __restrict__ out, int hid, float* __restrict__ sm)
{
    const int t = threadIdx.x;
    float* tile = sm;                 // [32][132]

    // Run index for output targets: g_xt_ready[0] == NHELP*run (+<NHELP
    // stragglers at most) when read here; division floors to run exactly.
    const unsigned run = atomicAdd(&g_xt_ready[0], 0u) / (unsigned)NHELP;

    // ---------------- INPUT: (B,C,H,W) -> g_Xt, chunk by chunk -------------
    for (int k = 0; k < NCHK; ++k) {
        const int w0 = k * CHKW;
        int idx = hid;
        float4 v[4];
        if (idx < TILES_PER_CHUNK) tin_preload(states, w0, idx, t, v);
        while (idx < TILES_PER_CHUNK) {
            const int nidx = idx + NHELP;
            // phase 1: registers -> smem tile
            {
                const int c = t >> 3, w8 = t & 7;
#pragma unroll
                for (int j = 0; j < 4; ++j)
                    *(float4*)&tile[c * 132 + w8 * 4 + j * 32] = v[j];
            }
            if (nidx < TILES_PER_CHUNK) tin_preload(states, w0, nidx, t, v);
            __syncthreads();
            // phase 2: smem tile -> g_Xt (c-contiguous)
            {
                const int h = idx & 511, b = idx >> 9;
                const int wl = t >> 1, chalf = t & 1;
                const size_t gb = ((size_t)((w0 + wl) * 8 + b) * 512 + h) * 32 + chalf * 16;
#pragma unroll
                for (int j = 0; j < 4; ++j) {
                    float4 u;
                    u.x = tile[(chalf * 16 + j * 4 + 0) * 132 + wl];
                    u.y = tile[(chalf * 16 + j * 4 + 1) * 132 + wl];
                    u.z = tile[(chalf * 16 + j * 4 + 2) * 132 + wl];
                    u.w = tile[(chalf * 16 + j * 4 + 3) * 132 + wl];
                    *(float4*)&g_Xt[gb + j * 4] = u;
                }
            }
            __syncthreads();
            idx = nidx;
        }
        if (t == 0) atom_rel_add(&g_xt_ready[k], 1u);   // after-bar release
    }

    // ---------------- OUTPUT: g_Yt -> (B,C,H,W), gated per chunk -----------
    const unsigned otgt = run * (unsigned)NBLK + (unsigned)NBLK;
    for (int k = 0; k < NCHK; ++k) {
        if (t == 0) {
            while (atomicAdd(&g_out_ready[k], 0u) < otgt) __nanosleep(500);
        }
        __syncthreads();
        const int w0 = k * CHKW;
        int idx = hid;
        float4 v[4];
        if (idx < TILES_PER_CHUNK) tout_preload(w0, idx, t, v);
        while (idx < TILES_PER_CHUNK) {
            const int nidx = idx + NHELP;
            // phase 1: registers -> smem tile (scatter to c-rows)
            {
                const int wl = t >> 1, chalf = t & 1;
#pragma unroll
                for (int j = 0; j < 4; ++j) {
                    tile[(chalf * 16 + j * 4 + 0) * 132 + wl] = v[j].x;
                    tile[(chalf * 16 + j * 4 + 1) * 132 + wl] = v[j].y;
                    tile[(chalf * 16 + j * 4 + 2) * 132 + wl] = v[j].z;
                    tile[(chalf * 16 + j * 4 + 3) * 132 + wl] = v[j].w;
                }
            }
            if (nidx < TILES_PER_CHUNK) tout_preload(w0, nidx, t, v);
            __syncthreads();
            // phase 2: smem tile -> out (w-contiguous)
            {
                const int h = idx & 511, b = idx >> 9;
                const int c = t >> 3, w8 = t & 7;
                const size_t base = ((size_t)(b * 32 + c) * 512 + h) * 512 + w0;
#pragma unroll
                for (int j = 0; j < 4; ++j) {
                    const int wl = w8 * 4 + j * 32;
                    *(float4*)&out[base + wl] = *(const float4*)&tile[c * 132 + wl];
                }
            }
            __syncthreads();
            idx = nidx;
        }
    }
}

// ===========================================================================
// SCAN BLOCKS — R10/R12-proven body; additions: 4 input-chunk gates and
// 4 output-chunk ready bumps (leader-only, off the hot path).
// ===========================================================================
__device__ __forceinline__ void scan_gate_chunk(int chunk, unsigned run, int tid) {
    if (tid == 0) {
        const unsigned tgt = run * (unsigned)NHELP + (unsigned)NHELP;
        while (atomicAdd(&g_xt_ready[chunk], 0u) < tgt) { }
    }
    __syncthreads();
}

template<int PREV, int NEXT>
__device__ __forceinline__ void gru_step(
    float* __restrict__ sm, int w, float4& xnext,
    int tid, int b, int tile, int h0, int c, int rq, int beta,
    unsigned sBase, unsigned run,
    float br0, float bz0, float bni, float bnh)
{
    // Gate before prefetching into a not-yet-transposed input chunk
    if (((w + 1) & (CHKW - 1)) == 0 && (w + 1) < W_DIM)
        scan_gate_chunk((w + 1) >> 7, run, tid);

    // Own-row input-column store from prefetch register; issue next prefetch
    ((float4*)(sm + SM_CUR))[tid] = xnext;
    if (w + 1 < W_DIM)
        xnext = *(const float4*)&g_Xt[((size_t)((w + 1) * 8 + b) * 512 + h0) * 32 + tid * 4];

    // Edge warps fetch their own halo row of column w-1
    if (rq == 0) {
        if (tile > 0) {
            if ((tid & 31) == 0) {
                const unsigned tgt = sBase + (unsigned)w;
                while (atomicAdd(&g_progress[beta - 1], 0u) < tgt) { }
            }
            __syncwarp();
            float v = __ldcg(&g_Yt[((size_t)((w - 1) * 8 + b) * 512 + (h0 - 1)) * 32 + (tid & 31)]);
            sm[PREV + (tid & 31)] = v;                     // slot 0
        }
    } else if (rq == 7) {
        if (tile < 15) {
            if ((tid & 31) == 0) {
                const unsigned tgt = sBase + (unsigned)w;
                while (atomicAdd(&g_progress[beta + 1], 0u) < tgt) { }
            }
            __syncwarp();
            float v = __ldcg(&g_Yt[((size_t)((w - 1) * 8 + b) * 512 + (h0 + 32)) * 32 + (tid & 31)]);
            sm[PREV + 33 * 32 + (tid & 31)] = v;           // slot 33
        }
    }
    __syncwarp();   // cross-lane visibility of sCur rows + own halo slot

    // ---- compute: 4 rows x 1 channel per thread ---------------------------
    float ar[4], az[4], ani[4], anh[4];
#pragma unroll
    for (int i = 0; i < 4; ++i) { ar[i] = br0; az[i] = bz0; ani[i] = bni; anh[i] = bnh; }

#pragma unroll 8
    for (int kq = 0; kq < 24; ++kq) {
        float4 wr = *(const float4*)&sm[SM_WIH + (c)      * 100 + kq * 4];
        float4 wz = *(const float4*)&sm[SM_WIH + (32 + c) * 100 + kq * 4];
        float4 wn = *(const float4*)&sm[SM_WIH + (64 + c) * 100 + kq * 4];
#pragma unroll
        for (int i = 0; i < 4; ++i) {
            float4 xv = *(const float4*)&sm[PREV + (rq * 4 + i) * 32 + kq * 4];
            ar[i]  = fmaf(xv.x, wr.x, fmaf(xv.y, wr.y, fmaf(xv.z, wr.z, fmaf(xv.w, wr.w, ar[i]))));
            az[i]  = fmaf(xv.x, wz.x, fmaf(xv.y, wz.y, fmaf(xv.z, wz.z, fmaf(xv.w, wz.w, az[i]))));
            ani[i] = fmaf(xv.x, wn.x, fmaf(xv.y, wn.y, fmaf(xv.z, wn.z, fmaf(xv.w, wn.w, ani[i]))));
        }
    }
#pragma unroll
    for (int kq = 0; kq < 8; ++kq) {
        float4 wr = *(const float4*)&sm[SM_WHH + (c)      * 36 + kq * 4];
        float4 wz = *(const float4*)&sm[SM_WHH + (32 + c) * 36 + kq * 4];
        float4 wn = *(const float4*)&sm[SM_WHH + (64 + c) * 36 + kq * 4];
#pragma unroll
        for (int i = 0; i < 4; ++i) {
            float4 hv = *(const float4*)&sm[SM_CUR + (rq * 4 + i) * 32 + kq * 4];
            ar[i]  = fmaf(hv.x, wr.x, fmaf(hv.y, wr.y, fmaf(hv.z, wr.z, fmaf(hv.w, wr.w, ar[i]))));
            az[i]  = fmaf(hv.x, wz.x, fmaf(hv.y, wz.y, fmaf(hv.z, wz.z, fmaf(hv.w, wz.w, az[i]))));
            anh[i] = fmaf(hv.x, wn.x, fmaf(hv.y, wn.y, fmaf(hv.z, wn.z, fmaf(hv.w, wn.w, anh[i]))));
        }
    }

    float outv[4];
#pragma unroll
    for (int i = 0; i < 4; ++i) {
        float rg = sigmoid_fast(ar[i]);
        float zg = sigmoid_fast(az[i]);
        float ng = tanh_fast(fmaf(rg, anh[i], ani[i]));
        float cv = sm[SM_CUR + (rq * 4 + i) * 32 + c];
        outv[i]  = fmaf(ng - cv, zg, cv);   // n*z + cur*(1-z)
    }

#pragma unroll
    for (int i = 0; i < 4; ++i) {
        int r = rq * 4 + i;
        sm[NEXT + (1 + r) * 32 + c] = outv[i];
        g_Yt[((size_t)(w * 8 + b) * 512 + (h0 + r)) * 32 + c] = outv[i];
    }
    __syncthreads();   // the ONLY block barrier: tile handoff + happens-before
    if (tid == 0) {
        atom_rel_exch(&g_progress[beta], sBase + (unsigned)(w + 1));
        if ((w & (CHKW - 1)) == CHKW - 1)            // w = 127/255/383/511
            atom_rel_add(&g_out_ready[w >> 7], 1u);
    }
}

__device__ void scan_body(
    const float* __restrict__ Wih, const float* __restrict__ bih,
    const float* __restrict__ Whh, const float* __restrict__ bhh,
    float* __restrict__ sm)
{
    __shared__ unsigned sBaseSh;

    const int tid  = threadIdx.x;
    const int beta = blockIdx.x;
    const int b    = beta >> 4;
    const int tile = beta & 15;
    const int h0   = tile * 32;
    const int c    = tid & 31;
    const int rq   = tid >> 5;

    if (tid == 0) sBaseSh = atomicAdd(&g_progress[beta], 0u);

    for (int i = tid; i < 96 * 96; i += NTHR) sm[SM_WIH + (i / 96) * 100 + (i % 96)] = Wih[i];
    for (int i = tid; i < 96 * 32; i += NTHR) sm[SM_WHH + (i / 32) * 36  + (i % 32)] = Whh[i];

    const float br0 = bih[c]      + bhh[c];
    const float bz0 = bih[32 + c] + bhh[32 + c];
    const float bni = bih[64 + c];
    const float bnh = bhh[64 + c];

    if (tid < 32) { sm[SM_BUFA + tid] = 0.0f; sm[SM_BUFB + tid] = 0.0f; }
    else if (tid < 64) {
        sm[SM_BUFA + 33 * 32 + (tid - 32)] = 0.0f;
        sm[SM_BUFB + 33 * 32 + (tid - 32)] = 0.0f;
    }
    __syncthreads();
    const unsigned sBase = sBaseSh;
    const unsigned run   = sBase >> 9;     // g_progress advances +512 per run

    // Wait for input chunk 0 (cols 0..127) before touching g_Xt
    scan_gate_chunk(0, run, tid);

    // Publish column 0 = input column 0 (identity passthrough) into bufA
    for (int i = tid; i < 1024; i += NTHR) {
        int r = i >> 5, cc = i & 31;
        size_t gi = ((size_t)b * 512 + (h0 + r)) * 32 + cc;   // w = 0
        float v = g_Xt[gi];
        sm[SM_BUFA + (1 + r) * 32 + cc] = v;
        g_Yt[gi] = v;
    }
    __syncthreads();
    if (tid == 0) atom_rel_exch(&g_progress[beta], sBase + 1);

    float4 xnext = *(const float4*)&g_Xt[((size_t)(1 * 8 + b) * 512 + h0) * 32 + tid * 4];

    gru_step<SM_BUFA, SM_BUFB>(sm, 1, xnext, tid, b, tile, h0, c, rq, beta,
                               sBase, run, br0, bz0, bni, bnh);
    for (int w = 2; w < W_DIM; w += 2) {
        gru_step<SM_BUFB, SM_BUFA>(sm, w,     xnext, tid, b, tile, h0, c, rq, beta,
                                   sBase, run, br0, bz0, bni, bnh);
        gru_step<SM_BUFA, SM_BUFB>(sm, w + 1, xnext, tid, b, tile, h0, c, rq, beta,
                                   sBase, run, br0, bz0, bni, bnh);
    }
}

// ===========================================================================
// Fused kernel: blocks 0..127 scan, 128..147 transpose helpers. 148 blocks =
// 148 SMs, all wave-1 resident -> spin-free progress guaranteed.
// ===========================================================================
__global__ __launch_bounds__(NTHR, 1) void fused_kernel(
    const float* __restrict__ states, float* __restrict__ out,
    const float* __restrict__ Wih, const float* __restrict__ bih,
    const float* __restrict__ Whh, const float* __restrict__ bhh)
{
    extern __shared__ float sm[];
    if (blockIdx.x < NBLK)
        scan_body(Wih, bih, Whh, bhh, sm);
    else
        helper_body(states, out, blockIdx.x - NBLK, sm);
}

// ---------------------------------------------------------------------------
extern "C" void kernel_launch(void* const* d_in, const int* in_sizes, int n_in,
                              void* d_out, int out_size) {
    const float* states = (const float*)d_in[0];
    const float* wih    = (const float*)d_in[1];
    const float* bih    = (const float*)d_in[2];
    const float* whh    = (const float*)d_in[3];
    const float* bhh    = (const float*)d_in[4];
    float* out = (float*)d_out;

    cudaFuncSetAttribute(fused_kernel, cudaFuncAttributeMaxDynamicSharedMemorySize,
                         SM_FLOATS * (int)sizeof(float));

    fused_kernel<<<NBLK + NHELP, NTHR, SM_FLOATS * sizeof(float)>>>(
        states, out, wih, bih, whh, bhh);
}

// round 15
// speedup vs baseline: 1.1411x; 1.1411x over previous
#include <cuda_runtime.h>

// Problem constants
#define W_DIM 512
#define H_DIM 512
#define B_DIM 8
#define C_DIM 32
#define NBLK  128           // scan blocks: 8 batches * 16 row-tiles
#define NHELP 20            // helper blocks on otherwise-idle SMs
#define NTOT  (NBLK + NHELP)
#define NTHR  256
#define NCHK  4             // w-chunks of 128 columns
#define CHKW  128
#define TILES_PER_CHUNK (H_DIM * B_DIM)   // 4096 tiles (128w x 32c each)

// Scratch: transposed input/output in (W, B, H, C) layout, C contiguous.
__device__ float    g_Xt[W_DIM * B_DIM * H_DIM * C_DIM];   // 256 MB
__device__ float    g_Yt[W_DIM * B_DIM * H_DIM * C_DIM];   // 256 MB
__device__ unsigned g_progress[NBLK];    // monotonic, +512/run (proven)
__device__ unsigned g_in0_done;          // monotonic, +NTOT/run
__device__ unsigned g_xt_ready[3];       // chunks 1..3, monotonic +NHELP/run
__device__ unsigned g_out_ready[NCHK];   // monotonic, +NBLK/run

// ---- fast math -------------------------------------------------------------
__device__ __forceinline__ float tanh_fast(float x) {
    float y; asm("tanh.approx.f32 %0, %1;" : "=f"(y) : "f"(x)); return y;
}
__device__ __forceinline__ float sigmoid_fast(float x) {
    return fmaf(0.5f, tanh_fast(0.5f * x), 0.5f);
}

// Release-ordered atomics at GPU scope (proven R10/R12/R14 protocol).
__device__ __forceinline__ void atom_rel_exch(unsigned* p, unsigned v) {
    unsigned old;
    asm volatile("atom.release.gpu.global.exch.b32 %0, [%1], %2;"
                 : "=r"(old) : "l"(p), "r"(v) : "memory");
}
__device__ __forceinline__ void atom_rel_add(unsigned* p, unsigned v) {
    unsigned old;
    asm volatile("atom.release.gpu.global.add.u32 %0, [%1], %2;"
                 : "=r"(old) : "l"(p), "r"(v) : "memory");
}

// ---------------------------------------------------------------------------
// smem layout (floats) — scan blocks. The SM_WIH region (9600 floats) also
// serves as the 32x132 transpose tile (4224 floats) during head/tail phases
// (before weights are loaded / after the scan is done).
// ---------------------------------------------------------------------------
#define SM_WIH  0
#define SM_WHH  (SM_WIH + 96 * 100)
#define SM_BUFA (SM_WHH + 96 * 36)
#define SM_BUFB (SM_BUFA + 34 * 32)
#define SM_CUR  (SM_BUFB + 34 * 32)
#define SM_FLOATS (SM_CUR + 32 * 32)

// ===========================================================================
// Transpose tile workers (R12/R14-proven phases, software-pipelined preload)
// ===========================================================================
__device__ __forceinline__ void tin_preload(
    const float* __restrict__ states, int w0, int idx, int t, float4 v[4])
{
    const int h = idx & 511, b = idx >> 9;
    const int c = t >> 3, w8 = t & 7;
    const size_t base = ((size_t)(b * 32 + c) * 512 + h) * 512 + w0;
#pragma unroll
    for (int k = 0; k < 4; ++k)
        v[k] = *(const float4*)&states[base + w8 * 4 + k * 32];
}

__device__ __forceinline__ void tout_preload(int w0, int idx, int t, float4 v[4])
{
    const int h = idx & 511, b = idx >> 9;
    const int wl = t >> 1, chalf = t & 1;
    const size_t base = ((size_t)((w0 + wl) * 8 + b) * 512 + h) * 32 + chalf * 16;
#pragma unroll
    for (int k = 0; k < 4; ++k)
        v[k] = __ldcg((const float4*)&g_Yt[base + k * 4]);   // L2-coherent
}

// (B,C,H,W) chunk -> g_Xt, tiles start, start+stride, ...
__device__ void tin_tiles(const float* __restrict__ states, int w0,
                          int start, int stride, int t, float* __restrict__ tile)
{
    int idx = start;
    float4 v[4];
    if (idx < TILES_PER_CHUNK) tin_preload(states, w0, idx, t, v);
    while (idx < TILES_PER_CHUNK) {
        const int nidx = idx + stride;
        {   // phase 1: registers -> smem tile
            const int c = t >> 3, w8 = t & 7;
#pragma unroll
            for (int j = 0; j < 4; ++j)
                *(float4*)&tile[c * 132 + w8 * 4 + j * 32] = v[j];
        }
        if (nidx < TILES_PER_CHUNK) tin_preload(states, w0, nidx, t, v);
        __syncthreads();
        {   // phase 2: smem tile -> g_Xt (c-contiguous)
            const int h = idx & 511, b = idx >> 9;
            const int wl = t >> 1, chalf = t & 1;
            const size_t gb = ((size_t)((w0 + wl) * 8 + b) * 512 + h) * 32 + chalf * 16;
#pragma unroll
            for (int j = 0; j < 4; ++j) {
                float4 u;
                u.x = tile[(chalf * 16 + j * 4 + 0) * 132 + wl];
                u.y = tile[(chalf * 16 + j * 4 + 1) * 132 + wl];
                u.z = tile[(chalf * 16 + j * 4 + 2) * 132 + wl];
                u.w = tile[(chalf * 16 + j * 4 + 3) * 132 + wl];
                *(float4*)&g_Xt[gb + j * 4] = u;
            }
        }
        __syncthreads();
        idx = nidx;
    }
}

// g_Yt chunk -> out (B,C,H,W), tiles start, start+stride, ...
__device__ void tout_tiles(float* __restrict__ out, int w0,
                           int start, int stride, int t, float* __restrict__ tile)
{
    int idx = start;
    float4 v[4];
    if (idx < TILES_PER_CHUNK) tout_preload(w0, idx, t, v);
    while (idx < TILES_PER_CHUNK) {
        const int nidx = idx + stride;
        {   // phase 1: registers -> smem tile (scatter to c-rows)
            const int wl = t >> 1, chalf = t & 1;
#pragma unroll
            for (int j = 0; j < 4; ++j) {
                tile[(chalf * 16 + j * 4 + 0) * 132 + wl] = v[j].x;
                tile[(chalf * 16 + j * 4 + 1) * 132 + wl] = v[j].y;
                tile[(chalf * 16 + j * 4 + 2) * 132 + wl] = v[j].z;
                tile[(chalf * 16 + j * 4 + 3) * 132 + wl] = v[j].w;
            }
        }
        if (nidx < TILES_PER_CHUNK) tout_preload(w0, nidx, t, v);
        __syncthreads();
        {   // phase 2: smem tile -> out (w-contiguous)
            const int h = idx & 511, b = idx >> 9;
            const int c = t >> 3, w8 = t & 7;
            const size_t base = ((size_t)(b * 32 + c) * 512 + h) * 512 + w0;
#pragma unroll
            for (int j = 0; j < 4; ++j) {
                const int wl = w8 * 4 + j * 32;
                *(float4*)&out[base + wl] = *(const float4*)&tile[c * 132 + wl];
            }
        }
        __syncthreads();
        idx = nidx;
    }
}

// ===========================================================================
// HELPER BLOCKS
// ===========================================================================
__device__ void helper_body(const float* __restrict__ states,
                            float* __restrict__ out, float* __restrict__ sm)
{
    const int t   = threadIdx.x;
    const int hid = blockIdx.x - NBLK;
    float* tile = sm;

    // Run index: g_progress[0] can only advance after chunk 0 completes,
    // which needs THIS block's contribution -> read here is exactly 512*run.
    const unsigned run = atomicAdd(&g_progress[0], 0u) >> 9;

    // Head: cooperative input chunk 0 (all 148 blocks)
    tin_tiles(states, 0, blockIdx.x, NTOT, t, tile);
    __syncthreads();
    if (t == 0) atom_rel_add(&g_in0_done, 1u);

    // Middle: input chunks 1..3 (helpers only)
    for (int k = 1; k < NCHK; ++k) {
        tin_tiles(states, k * CHKW, hid, NHELP, t, tile);
        __syncthreads();
        if (t == 0) atom_rel_add(&g_xt_ready[k - 1], 1u);
    }

    // Middle: output chunks 0..2 (helpers only, gated on scan progress)
    const unsigned otgt = (run + 1u) * (unsigned)NBLK;
    for (int k = 0; k < 3; ++k) {
        if (t == 0) {
            while (atomicAdd(&g_out_ready[k], 0u) < otgt) __nanosleep(500);
        }
        __syncthreads();
        tout_tiles(out, k * CHKW, hid, NHELP, t, tile);
    }

    // Tail: cooperative output chunk 3 (all 148 blocks)
    if (t == 0) {
        while (atomicAdd(&g_out_ready[3], 0u) < otgt) __nanosleep(500);
    }
    __syncthreads();
    tout_tiles(out, 3 * CHKW, blockIdx.x, NTOT, t, tile);
}

// ===========================================================================
// SCAN BLOCKS — R10/R12-proven step body (byte-identical hot loop)
// ===========================================================================
template<int PREV, int NEXT>
__device__ __forceinline__ void gru_step(
    float* __restrict__ sm, int w, float4& xnext,
    int tid, int b, int tile, int h0, int c, int rq, int beta,
    unsigned sBase, unsigned run,
    float br0, float bz0, float bni, float bnh)
{
    // Gate before prefetching into a not-yet-transposed input chunk
    if (((w + 1) & (CHKW - 1)) == 0 && (w + 1) < W_DIM) {
        if (tid == 0) {
            const unsigned tgt = (run + 1u) * (unsigned)NHELP;
            while (atomicAdd(&g_xt_ready[((w + 1) >> 7) - 1], 0u) < tgt) { }
        }
        __syncthreads();
    }

    // Own-row input-column store from prefetch register; issue next prefetch
    ((float4*)(sm + SM_CUR))[tid] = xnext;
    if (w + 1 < W_DIM)
        xnext = *(const float4*)&g_Xt[((size_t)((w + 1) * 8 + b) * 512 + h0) * 32 + tid * 4];

    // Edge warps fetch their own halo row of column w-1
    if (rq == 0) {
        if (tile > 0) {
            if ((tid & 31) == 0) {
                const unsigned tgt = sBase + (unsigned)w;
                while (atomicAdd(&g_progress[beta - 1], 0u) < tgt) { }
            }
            __syncwarp();
            float v = __ldcg(&g_Yt[((size_t)((w - 1) * 8 + b) * 512 + (h0 - 1)) * 32 + (tid & 31)]);
            sm[PREV + (tid & 31)] = v;                     // slot 0
        }
    } else if (rq == 7) {
        if (tile < 15) {
            if ((tid & 31) == 0) {
                const unsigned tgt = sBase + (unsigned)w;
                while (atomicAdd(&g_progress[beta + 1], 0u) < tgt) { }
            }
            __syncwarp();
            float v = __ldcg(&g_Yt[((size_t)((w - 1) * 8 + b) * 512 + (h0 + 32)) * 32 + (tid & 31)]);
            sm[PREV + 33 * 32 + (tid & 31)] = v;           // slot 33
        }
    }
    __syncwarp();   // cross-lane visibility of sCur rows + own halo slot

    // ---- compute: 4 rows x 1 channel per thread ---------------------------
    float ar[4], az[4], ani[4], anh[4];
#pragma unroll
    for (int i = 0; i < 4; ++i) { ar[i] = br0; az[i] = bz0; ani[i] = bni; anh[i] = bnh; }

#pragma unroll 8
    for (int kq = 0; kq < 24; ++kq) {
        float4 wr = *(const float4*)&sm[SM_WIH + (c)      * 100 + kq * 4];
        float4 wz = *(const float4*)&sm[SM_WIH + (32 + c) * 100 + kq * 4];
        float4 wn = *(const float4*)&sm[SM_WIH + (64 + c) * 100 + kq * 4];
#pragma unroll
        for (int i = 0; i < 4; ++i) {
            float4 xv = *(const float4*)&sm[PREV + (rq * 4 + i) * 32 + kq * 4];
            ar[i]  = fmaf(xv.x, wr.x, fmaf(xv.y, wr.y, fmaf(xv.z, wr.z, fmaf(xv.w, wr.w, ar[i]))));
            az[i]  = fmaf(xv.x, wz.x, fmaf(xv.y, wz.y, fmaf(xv.z, wz.z, fmaf(xv.w, wz.w, az[i]))));
            ani[i] = fmaf(xv.x, wn.x, fmaf(xv.y, wn.y, fmaf(xv.z, wn.z, fmaf(xv.w, wn.w, ani[i]))));
        }
    }
#pragma unroll
    for (int kq = 0; kq < 8; ++kq) {
        float4 wr = *(const float4*)&sm[SM_WHH + (c)      * 36 + kq * 4];
        float4 wz = *(const float4*)&sm[SM_WHH + (32 + c) * 36 + kq * 4];
        float4 wn = *(const float4*)&sm[SM_WHH + (64 + c) * 36 + kq * 4];
#pragma unroll
        for (int i = 0; i < 4; ++i) {
            float4 hv = *(const float4*)&sm[SM_CUR + (rq * 4 + i) * 32 + kq * 4];
            ar[i]  = fmaf(hv.x, wr.x, fmaf(hv.y, wr.y, fmaf(hv.z, wr.z, fmaf(hv.w, wr.w, ar[i]))));
            az[i]  = fmaf(hv.x, wz.x, fmaf(hv.y, wz.y, fmaf(hv.z, wz.z, fmaf(hv.w, wz.w, az[i]))));
            anh[i] = fmaf(hv.x, wn.x, fmaf(hv.y, wn.y, fmaf(hv.z, wn.z, fmaf(hv.w, wn.w, anh[i]))));
        }
    }

    float outv[4];
#pragma unroll
    for (int i = 0; i < 4; ++i) {
        float rg = sigmoid_fast(ar[i]);
        float zg = sigmoid_fast(az[i]);
        float ng = tanh_fast(fmaf(rg, anh[i], ani[i]));
        float cv = sm[SM_CUR + (rq * 4 + i) * 32 + c];
        outv[i]  = fmaf(ng - cv, zg, cv);   // n*z + cur*(1-z)
    }

#pragma unroll
    for (int i = 0; i < 4; ++i) {
        int r = rq * 4 + i;
        sm[NEXT + (1 + r) * 32 + c] = outv[i];
        g_Yt[((size_t)(w * 8 + b) * 512 + (h0 + r)) * 32 + c] = outv[i];
    }
    __syncthreads();   // the ONLY block barrier: tile handoff + happens-before
    if (tid == 0) {
        atom_rel_exch(&g_progress[beta], sBase + (unsigned)(w + 1));
        if ((w & (CHKW - 1)) == CHKW - 1)            // w = 127/255/383/511
            atom_rel_add(&g_out_ready[w >> 7], 1u);
    }
}

__device__ void scan_body(
    const float* __restrict__ states, float* __restrict__ out,
    const float* __restrict__ Wih, const float* __restrict__ bih,
    const float* __restrict__ Whh, const float* __restrict__ bhh,
    float* __restrict__ sm)
{
    __shared__ unsigned sBaseSh;

    const int tid  = threadIdx.x;
    const int beta = blockIdx.x;
    const int b    = beta >> 4;
    const int tile = beta & 15;
    const int h0   = tile * 32;
    const int c    = tid & 31;
    const int rq   = tid >> 5;

    if (tid == 0) sBaseSh = atomicAdd(&g_progress[beta], 0u);
    __syncthreads();
    const unsigned sBase = sBaseSh;
    const unsigned run   = sBase >> 9;     // g_progress advances +512 per run

    // Head: cooperative input chunk 0 (tile buffer = SM_WIH region, weights
    // not loaded yet)
    tin_tiles(states, 0, beta, NTOT, tid, sm + SM_WIH);
    __syncthreads();
    if (tid == 0) atom_rel_add(&g_in0_done, 1u);

    // Load weights (overlaps other blocks' chunk-0 stragglers)
    for (int i = tid; i < 96 * 96; i += NTHR) sm[SM_WIH + (i / 96) * 100 + (i % 96)] = Wih[i];
    for (int i = tid; i < 96 * 32; i += NTHR) sm[SM_WHH + (i / 32) * 36  + (i % 32)] = Whh[i];

    const float br0 = bih[c]      + bhh[c];
    const float bz0 = bih[32 + c] + bhh[32 + c];
    const float bni = bih[64 + c];
    const float bnh = bhh[64 + c];

    if (tid < 32) { sm[SM_BUFA + tid] = 0.0f; sm[SM_BUFB + tid] = 0.0f; }
    else if (tid < 64) {
        sm[SM_BUFA + 33 * 32 + (tid - 32)] = 0.0f;
        sm[SM_BUFB + 33 * 32 + (tid - 32)] = 0.0f;
    }

    // Wait until ALL blocks finished input chunk 0
    if (tid == 0) {
        const unsigned tgt = (run + 1u) * (unsigned)NTOT;
        while (atomicAdd(&g_in0_done, 0u) < tgt) { }
    }
    __syncthreads();

    // Publish column 0 = input column 0 (identity passthrough) into bufA
    for (int i = tid; i < 1024; i += NTHR) {
        int r = i >> 5, cc = i & 31;
        size_t gi = ((size_t)b * 512 + (h0 + r)) * 32 + cc;   // w = 0
        float v = g_Xt[gi];
        sm[SM_BUFA + (1 + r) * 32 + cc] = v;
        g_Yt[gi] = v;
    }
    __syncthreads();
    if (tid == 0) atom_rel_exch(&g_progress[beta], sBase + 1);

    float4 xnext = *(const float4*)&g_Xt[((size_t)(1 * 8 + b) * 512 + h0) * 32 + tid * 4];

    gru_step<SM_BUFA, SM_BUFB>(sm, 1, xnext, tid, b, tile, h0, c, rq, beta,
                               sBase, run, br0, bz0, bni, bnh);
    for (int w = 2; w < W_DIM; w += 2) {
        gru_step<SM_BUFB, SM_BUFA>(sm, w,     xnext, tid, b, tile, h0, c, rq, beta,
                                   sBase, run, br0, bz0, bni, bnh);
        gru_step<SM_BUFA, SM_BUFB>(sm, w + 1, xnext, tid, b, tile, h0, c, rq, beta,
                                   sBase, run, br0, bz0, bni, bnh);
    }

    // Tail: join the cooperative output transpose of chunk 3
    if (tid == 0) {
        const unsigned tgt = (run + 1u) * (unsigned)NBLK;
        while (atomicAdd(&g_out_ready[3], 0u) < tgt) { }
    }
    __syncthreads();
    tout_tiles(out, 3 * CHKW, beta, NTOT, tid, sm + SM_WIH);
}

// ===========================================================================
// Fused kernel: blocks 0..127 scan, 128..147 helpers. 148 blocks = 148 SMs,
// all wave-1 resident -> spin-free progress guaranteed.
// ===========================================================================
__global__ __launch_bounds__(NTHR, 1) void fused_kernel(
    const float* __restrict__ states, float* __restrict__ out,
    const float* __restrict__ Wih, const float* __restrict__ bih,
    const float* __restrict__ Whh, const float* __restrict__ bhh)
{
    extern __shared__ float sm[];
    if (blockIdx.x < NBLK)
        scan_body(states, out, Wih, bih, Whh, bhh, sm);
    else
        helper_body(states, out, sm);
}

// ---------------------------------------------------------------------------
extern "C" void kernel_launch(void* const* d_in, const int* in_sizes, int n_in,
                              void* d_out, int out_size) {
    const float* states = (const float*)d_in[0];
    const float* wih    = (const float*)d_in[1];
    const float* bih    = (const float*)d_in[2];
    const float* whh    = (const float*)d_in[3];
    const float* bhh    = (const float*)d_in[4];
    float* out = (float*)d_out;

    cudaFuncSetAttribute(fused_kernel, cudaFuncAttributeMaxDynamicSharedMemorySize,
                         SM_FLOATS * (int)sizeof(float));

    fused_kernel<<<NTOT, NTHR, SM_FLOATS * sizeof(float)>>>(
        states, out, wih, bih, whh, bhh);
}